// round 5
// baseline (speedup 1.0000x reference)
#include <cuda_runtime.h>

#define N_NODES 100000
#define N_RELS  200
#define D       200
#define BN_EPS  1e-5f

// ---------------- scratch (no cudaMalloc allowed) ----------------
// A[0] = in-edge accumulator, A[1] = out-edge accumulator  (160 MB total)
__device__ float g_A[2][(size_t)N_NODES * D];
__device__ float g_sum[D];
__device__ float g_sq[D];

// ---------------- zero scratch ----------------
__global__ void k_zero() {
    float4* p = (float4*)&g_A[0][0];
    size_t n4 = (size_t)2 * N_NODES * D / 4;   // 10,000,000 exactly
    size_t stride = (size_t)gridDim.x * blockDim.x;
    for (size_t i = (size_t)blockIdx.x * blockDim.x + threadIdx.x; i < n4; i += stride)
        p[i] = make_float4(0.f, 0.f, 0.f, 0.f);
    if (blockIdx.x == 0 && threadIdx.x < D) {
        g_sum[threadIdx.x] = 0.f;
        g_sq[threadIdx.x]  = 0.f;
    }
}

// ---------------- edge scatter: A[half][dst] += x[src]*rel[type]*(norm/3) ----------------
// one warp per edge; lanes cover the 50 float4 chunks of a 200-float row
__global__ void k_scatter(const float* __restrict__ x,
                          const float* __restrict__ rel,
                          const float* __restrict__ enorm,
                          const int*  __restrict__ esrc,
                          const int*  __restrict__ edst,
                          const int*  __restrict__ etyp,
                          int E, int half) {
    int w    = (blockIdx.x * blockDim.x + threadIdx.x) >> 5;
    int lane = threadIdx.x & 31;
    if (w >= E) return;
    int s = esrc[w];
    int d = edst[w];
    int t = etyp[w];
    float c = enorm[w] * (1.f / 3.f);
    const float4* xr = (const float4*)(x   + (size_t)s * D);
    const float4* rr = (const float4*)(rel + (size_t)t * D);
    float* a = (w < half ? g_A[0] : g_A[1]) + (size_t)d * D;
    #pragma unroll
    for (int i = lane; i < D / 4; i += 32) {
        float4 xv = xr[i];
        float4 rv = rr[i];
        atomicAdd(a + 4 * i + 0, xv.x * rv.x * c);
        atomicAdd(a + 4 * i + 1, xv.y * rv.y * c);
        atomicAdd(a + 4 * i + 2, xv.z * rv.z * c);
        atomicAdd(a + 4 * i + 3, xv.w * rv.w * c);
    }
}

// ---------------- node GEMM: h = A_in@in_w + A_out@out_w + (x*loop_rel/3)@loop_w ----------------
// BM=80 rows/block, K runs over 3 segments of 200. 320 threads, 10x5 register tile.
#define BM 80
#define KC 8
#define TM 10
#define TN 5

__global__ __launch_bounds__(320, 2)
void k_gemm(const float* __restrict__ x,
            const float* __restrict__ loop_rel,
            const float* __restrict__ in_w,
            const float* __restrict__ out_w,
            const float* __restrict__ loop_w,
            float* __restrict__ h) {
    __shared__ float As[BM * KC];     // [row][k]
    __shared__ float Bs[KC * D];      // [k][col]

    int tid = threadIdx.x;
    int tx  = tid % 40;               // col group: cols tx*5 .. tx*5+4
    int ty  = tid / 40;               // row group: rows ty*10 .. ty*10+9
    int row0 = blockIdx.x * BM;

    float acc[TM][TN];
    #pragma unroll
    for (int i = 0; i < TM; i++)
        #pragma unroll
        for (int j = 0; j < TN; j++) acc[i][j] = 0.f;

    const float* Asrc[3] = { g_A[0], g_A[1], x };
    const float* Bsrc[3] = { in_w,   out_w,  loop_w };

    for (int seg = 0; seg < 3; seg++) {
        const float* Ap = Asrc[seg];
        const float* Bp = Bsrc[seg];
        bool isx = (seg == 2);
        for (int kb = 0; kb < D; kb += KC) {
            // A tile: 80x8 = 640 floats, 2 per thread
            #pragma unroll
            for (int l = 0; l < 2; l++) {
                int idx = tid + l * 320;
                int r = idx >> 3, k = idx & 7;
                float v = Ap[(size_t)(row0 + r) * D + kb + k];
                if (isx) v *= loop_rel[kb + k] * (1.f / 3.f);
                As[idx] = v;
            }
            // B tile: 8x200 = 1600 floats, 5 per thread
            #pragma unroll
            for (int l = 0; l < 5; l++) {
                int idx = tid + l * 320;
                int k = idx / 200, c = idx % 200;
                Bs[idx] = Bp[(size_t)(kb + k) * D + c];
            }
            __syncthreads();
            #pragma unroll
            for (int k = 0; k < KC; k++) {
                float a[TM], b[TN];
                #pragma unroll
                for (int i = 0; i < TM; i++) a[i] = As[(ty * TM + i) * KC + k];
                #pragma unroll
                for (int j = 0; j < TN; j++) b[j] = Bs[k * D + tx * TN + j];
                #pragma unroll
                for (int i = 0; i < TM; i++)
                    #pragma unroll
                    for (int j = 0; j < TN; j++)
                        acc[i][j] = fmaf(a[i], b[j], acc[i][j]);
            }
            __syncthreads();
        }
    }

    #pragma unroll
    for (int i = 0; i < TM; i++)
        #pragma unroll
        for (int j = 0; j < TN; j++)
            h[(size_t)(row0 + ty * TM + i) * D + tx * TN + j] = acc[i][j];
}

// ---------------- per-column sum / sumsq for BatchNorm ----------------
// blockDim = 200: thread t owns column t; blocks stride over rows.
__global__ void k_stats(const float* __restrict__ h) {
    int col = threadIdx.x;
    float s = 0.f, q = 0.f;
    for (int r = blockIdx.x; r < N_NODES; r += gridDim.x) {
        float v = h[(size_t)r * D + col];
        s += v;
        q += v * v;
    }
    atomicAdd(&g_sum[col], s);
    atomicAdd(&g_sq[col],  q);
}

// ---------------- BatchNorm normalize (in place) ----------------
__global__ void k_norm(float* __restrict__ h,
                       const float* __restrict__ gamma,
                       const float* __restrict__ beta) {
    __shared__ float s_scale[D];
    __shared__ float s_shift[D];
    if (threadIdx.x < D) {
        const float invN = 1.f / (float)N_NODES;
        float mean = g_sum[threadIdx.x] * invN;
        float var  = g_sq[threadIdx.x] * invN - mean * mean;
        float inv  = rsqrtf(var + BN_EPS);
        float sc   = inv * gamma[threadIdx.x];
        s_scale[threadIdx.x] = sc;
        s_shift[threadIdx.x] = beta[threadIdx.x] - mean * sc;
    }
    __syncthreads();
    size_t n = (size_t)N_NODES * D;
    size_t stride = (size_t)gridDim.x * blockDim.x;
    for (size_t i = (size_t)blockIdx.x * blockDim.x + threadIdx.x; i < n; i += stride) {
        int col = (int)(i % D);
        h[i] = h[i] * s_scale[col] + s_shift[col];
    }
}

// ---------------- rel_out = rel_repr @ w_rel  (200x200x200, tiny) ----------------
__global__ void k_rel(const float* __restrict__ rel,
                      const float* __restrict__ w,
                      float* __restrict__ out) {
    int i = blockIdx.x;    // row
    int j = threadIdx.x;   // col
    float s = 0.f;
    #pragma unroll 4
    for (int k = 0; k < D; k++)
        s = fmaf(rel[i * D + k], w[k * D + j], s);
    out[i * D + j] = s;
}

// ---------------- launch ----------------
extern "C" void kernel_launch(void* const* d_in, const int* in_sizes, int n_in,
                              void* d_out, int out_size) {
    const float* x        = (const float*)d_in[0];
    const float* rel      = (const float*)d_in[1];
    const float* enorm    = (const float*)d_in[2];
    const float* in_w     = (const float*)d_in[3];
    const float* out_w    = (const float*)d_in[4];
    const float* loop_w   = (const float*)d_in[5];
    const float* loop_rel = (const float*)d_in[6];
    const float* w_rel    = (const float*)d_in[7];
    const float* gamma    = (const float*)d_in[8];
    const float* beta     = (const float*)d_in[9];
    const int*   esrc     = (const int*)d_in[10];
    const int*   edst     = (const int*)d_in[11];
    const int*   etyp     = (const int*)d_in[12];

    float* h      = (float*)d_out;
    float* relout = h + (size_t)N_NODES * D;

    int E = in_sizes[2];           // 400000
    int half = E / 2;

    k_zero<<<1024, 256>>>();
    k_scatter<<<(E + 7) / 8, 256>>>(x, rel, enorm, esrc, edst, etyp, E, half);
    k_gemm<<<N_NODES / BM, 320>>>(x, loop_rel, in_w, out_w, loop_w, h);
    k_stats<<<400, 200>>>(h);
    k_norm<<<1024, 256>>>(h, gamma, beta);
    k_rel<<<200, 200>>>(rel, w_rel, relout);
}

// round 6
// speedup vs baseline: 1.6358x; 1.6358x over previous
#include <cuda_runtime.h>
#include <cstdint>

#define N_NODES 100000
#define N_RELS  200
#define D       200
#define BN_EPS  1e-5f

// ---------------- scratch (no cudaMalloc allowed) ----------------
__device__ float g_A[2][(size_t)N_NODES * D];   // in / out edge accumulators
__device__ float g_sum[D];
__device__ float g_sq[D];

// packed f32x2 FMA: d = a*b + d  (sm_103a FFMA2, PTX-only)
#define FMA2(d, a, b) asm("fma.rn.f32x2 %0, %1, %2, %0;" : "+l"(d) : "l"(a), "l"(b))

// ---------------- zero scratch ----------------
__global__ void k_zero() {
    float4* p = (float4*)&g_A[0][0];
    size_t n4 = (size_t)2 * N_NODES * D / 4;   // 10,000,000
    size_t stride = (size_t)gridDim.x * blockDim.x;
    for (size_t i = (size_t)blockIdx.x * blockDim.x + threadIdx.x; i < n4; i += stride)
        p[i] = make_float4(0.f, 0.f, 0.f, 0.f);
    if (blockIdx.x == 0 && threadIdx.x < D) {
        g_sum[threadIdx.x] = 0.f;
        g_sq[threadIdx.x]  = 0.f;
    }
}

// ---------------- edge scatter: A[half][dst] += x[src]*rel[type]*(norm/3) ----------------
__global__ void k_scatter(const float* __restrict__ x,
                          const float* __restrict__ rel,
                          const float* __restrict__ enorm,
                          const int*  __restrict__ esrc,
                          const int*  __restrict__ edst,
                          const int*  __restrict__ etyp,
                          int E, int half) {
    int w    = (blockIdx.x * blockDim.x + threadIdx.x) >> 5;
    int lane = threadIdx.x & 31;
    if (w >= E) return;
    int s = esrc[w];
    int d = edst[w];
    int t = etyp[w];
    float c = enorm[w] * (1.f / 3.f);
    const float4* xr = (const float4*)(x   + (size_t)s * D);
    const float4* rr = (const float4*)(rel + (size_t)t * D);
    float* a = (w < half ? g_A[0] : g_A[1]) + (size_t)d * D;
    #pragma unroll
    for (int i = lane; i < D / 4; i += 32) {
        float4 xv = xr[i];
        float4 rv = rr[i];
        atomicAdd(a + 4 * i + 0, xv.x * rv.x * c);
        atomicAdd(a + 4 * i + 1, xv.y * rv.y * c);
        atomicAdd(a + 4 * i + 2, xv.z * rv.z * c);
        atomicAdd(a + 4 * i + 3, xv.w * rv.w * c);
    }
}

// ---------------- node GEMM with FFMA2 + fused BN stats ----------------
// h = A_in@in_w + A_out@out_w + (x*loop_rel/3)@loop_w ; also g_sum/g_sq per column.
// BM=80 rows/block (1250 blocks). 256 threads, 250 active:
//   ty = tid/25 (0..9) -> rows ty*8..ty*8+7 ; tx = tid%25
//   col pairs p = jp*25+tx (jp=0..3) -> cols 2p, 2p+1  (2p = jp*50 + 2*tx)
#define BM 80
#define KC 8
#define AS_STRIDE 164   // BM*2 + 4 pad (STS/LDS bank spread)

__global__ __launch_bounds__(256, 2)
void k_gemm(const float* __restrict__ x,
            const float* __restrict__ loop_rel,
            const float* __restrict__ in_w,
            const float* __restrict__ out_w,
            const float* __restrict__ loop_w,
            float* __restrict__ h) {
    __shared__ __align__(16) float  As[KC * AS_STRIDE];  // dup-broadcast: [k][2r]=[k][2r+1]=A
    __shared__ __align__(16) float2 Bs[KC * 100];        // [k][p] = (B[k][2p], B[k][2p+1])
    __shared__ float s_sum[D];
    __shared__ float s_sq[D];

    int tid = threadIdx.x;
    int tx  = tid % 25;
    int ty  = tid / 25;      // 0..10 (10 = idle group)
    int ty8 = ty * 8;
    int row0 = blockIdx.x * BM;
    bool active = (tid < 250);

    if (tid < D) { s_sum[tid] = 0.f; s_sq[tid] = 0.f; }

    uint64_t acc[8][4];
    #pragma unroll
    for (int i = 0; i < 8; i++)
        #pragma unroll
        for (int j = 0; j < 4; j++) acc[i][j] = 0ull;

    const float* Asrc[3] = { g_A[0], g_A[1], x };
    const float* Bsrc[3] = { in_w,   out_w,  loop_w };

    for (int seg = 0; seg < 3; seg++) {
        const float* Ap = Asrc[seg];
        const float* Bp = Bsrc[seg];
        bool isx = (seg == 2);
        for (int kb = 0; kb < D; kb += KC) {
            __syncthreads();
            // A tile: 640 values, duplicated -> float2 (v,v) stores
            #pragma unroll
            for (int l = 0; l < 3; l++) {
                int idx = tid + l * 256;
                if (idx < BM * KC) {
                    int r = idx >> 3, k = idx & 7;
                    float v = Ap[(size_t)(row0 + r) * D + kb + k];
                    if (isx) v *= loop_rel[kb + k] * (1.f / 3.f);
                    *(float2*)&As[k * AS_STRIDE + 2 * r] = make_float2(v, v);
                }
            }
            // B tile: 800 float2 (8 k-rows x 100 pairs)
            #pragma unroll
            for (int l = 0; l < 4; l++) {
                int idx = tid + l * 256;
                if (idx < KC * 100) {
                    int k = idx / 100, p = idx - k * 100;
                    Bs[idx] = *(const float2*)(Bp + (size_t)(kb + k) * D + 2 * p);
                }
            }
            __syncthreads();
            if (active) {
                #pragma unroll
                for (int k = 0; k < KC; k++) {
                    uint64_t b[4], a[8];
                    #pragma unroll
                    for (int jp = 0; jp < 4; jp++)
                        b[jp] = *(const uint64_t*)&Bs[k * 100 + jp * 25 + tx];
                    #pragma unroll
                    for (int i = 0; i < 8; i++)
                        a[i] = *(const uint64_t*)&As[k * AS_STRIDE + 2 * (ty8 + i)];
                    #pragma unroll
                    for (int i = 0; i < 8; i++)
                        #pragma unroll
                        for (int jp = 0; jp < 4; jp++)
                            FMA2(acc[i][jp], a[i], b[jp]);
                }
            }
        }
    }

    // epilogue: store h + per-column partial stats
    if (active) {
        float s0[4] = {0,0,0,0}, s1[4] = {0,0,0,0};
        float q0[4] = {0,0,0,0}, q1[4] = {0,0,0,0};
        #pragma unroll
        for (int i = 0; i < 8; i++) {
            int row = row0 + ty8 + i;
            #pragma unroll
            for (int jp = 0; jp < 4; jp++) {
                float lo = __uint_as_float((unsigned)(acc[i][jp] & 0xffffffffu));
                float hi = __uint_as_float((unsigned)(acc[i][jp] >> 32));
                *(float2*)&h[(size_t)row * D + jp * 50 + 2 * tx] = make_float2(lo, hi);
                s0[jp] += lo; q0[jp] += lo * lo;
                s1[jp] += hi; q1[jp] += hi * hi;
            }
        }
        #pragma unroll
        for (int jp = 0; jp < 4; jp++) {
            int c = jp * 50 + 2 * tx;
            atomicAdd(&s_sum[c],     s0[jp]);
            atomicAdd(&s_sq[c],      q0[jp]);
            atomicAdd(&s_sum[c + 1], s1[jp]);
            atomicAdd(&s_sq[c + 1],  q1[jp]);
        }
    }
    __syncthreads();
    if (tid < D) {
        atomicAdd(&g_sum[tid], s_sum[tid]);
        atomicAdd(&g_sq[tid],  s_sq[tid]);
    }
}

// ---------------- BatchNorm normalize (in place, float4) ----------------
__global__ void k_norm(float* __restrict__ h,
                       const float* __restrict__ gamma,
                       const float* __restrict__ beta) {
    __shared__ float s_scale[D];
    __shared__ float s_shift[D];
    if (threadIdx.x < D) {
        const float invN = 1.f / (float)N_NODES;
        float mean = g_sum[threadIdx.x] * invN;
        float var  = g_sq[threadIdx.x] * invN - mean * mean;
        float inv  = rsqrtf(var + BN_EPS);
        float sc   = inv * gamma[threadIdx.x];
        s_scale[threadIdx.x] = sc;
        s_shift[threadIdx.x] = beta[threadIdx.x] - mean * sc;
    }
    __syncthreads();
    float4* h4 = (float4*)h;
    size_t n4 = (size_t)N_NODES * D / 4;   // 5,000,000
    size_t stride = (size_t)gridDim.x * blockDim.x;
    for (size_t i = (size_t)blockIdx.x * blockDim.x + threadIdx.x; i < n4; i += stride) {
        int c = (int)((i * 4) % D);
        float4 v = h4[i];
        v.x = v.x * s_scale[c]     + s_shift[c];
        v.y = v.y * s_scale[c + 1] + s_shift[c + 1];
        v.z = v.z * s_scale[c + 2] + s_shift[c + 2];
        v.w = v.w * s_scale[c + 3] + s_shift[c + 3];
        h4[i] = v;
    }
}

// ---------------- rel_out = rel_repr @ w_rel (tiny) ----------------
__global__ void k_rel(const float* __restrict__ rel,
                      const float* __restrict__ w,
                      float* __restrict__ out) {
    int i = blockIdx.x;
    int j = threadIdx.x;
    float s = 0.f;
    #pragma unroll 4
    for (int k = 0; k < D; k++)
        s = fmaf(rel[i * D + k], w[k * D + j], s);
    out[i * D + j] = s;
}

// ---------------- launch ----------------
extern "C" void kernel_launch(void* const* d_in, const int* in_sizes, int n_in,
                              void* d_out, int out_size) {
    const float* x        = (const float*)d_in[0];
    const float* rel      = (const float*)d_in[1];
    const float* enorm    = (const float*)d_in[2];
    const float* in_w     = (const float*)d_in[3];
    const float* out_w    = (const float*)d_in[4];
    const float* loop_w   = (const float*)d_in[5];
    const float* loop_rel = (const float*)d_in[6];
    const float* w_rel    = (const float*)d_in[7];
    const float* gamma    = (const float*)d_in[8];
    const float* beta     = (const float*)d_in[9];
    const int*   esrc     = (const int*)d_in[10];
    const int*   edst     = (const int*)d_in[11];
    const int*   etyp     = (const int*)d_in[12];

    float* h      = (float*)d_out;
    float* relout = h + (size_t)N_NODES * D;

    int E = in_sizes[2];           // 400000
    int half = E / 2;

    k_zero<<<1024, 256>>>();
    k_scatter<<<(E + 7) / 8, 256>>>(x, rel, enorm, esrc, edst, etyp, E, half);
    k_gemm<<<N_NODES / BM, 256>>>(x, loop_rel, in_w, out_w, loop_w, h);
    k_norm<<<1024, 256>>>(h, gamma, beta);
    k_rel<<<200, 200>>>(rel, w_rel, relout);
}

// round 11
// speedup vs baseline: 4.6643x; 2.8514x over previous
#include <cuda_runtime.h>
#include <cuda_bf16.h>
#include <cstdint>

#define N_NODES 100000
#define N_RELS  200
#define D       200
#define BN_EPS  1e-5f

#define SEGW 208          // per-segment padded K (200 real + 8 zero)
#define KCAT 624          // 3 * SEGW
#define NCHUNK 39         // 39 chunks of K=16
#define NPAD 224          // padded N for the GEMM (200 real)
#define N_TILES 782       // ceil(100000/128)

// ---------------- scratch (no cudaMalloc allowed) ----------------
__device__ float g_A[2][(size_t)N_NODES * D];   // in / out edge accumulators
__device__ float g_sum[D];
__device__ float g_sq[D];
__device__ __nv_bfloat16 g_Bhi[200 * KCAT];     // weights, split-bf16, K-major [n][kcat]
__device__ __nv_bfloat16 g_Blo[200 * KCAT];

// ---------------- PTX helpers (base ISA only — no sm_103a features!) ----------------
__device__ __forceinline__ uint32_t smem_u32(const void* p) {
    uint32_t a;
    asm("{ .reg .u64 t; cvta.to.shared.u64 t, %1; cvt.u32.u64 %0, t; }" : "=r"(a) : "l"(p));
    return a;
}

#define LDSM4(r, addr) \
    asm volatile("ldmatrix.sync.aligned.m8n8.x4.shared.b16 {%0,%1,%2,%3}, [%4];" \
                 : "=r"((r)[0]), "=r"((r)[1]), "=r"((r)[2]), "=r"((r)[3]) : "r"(addr))
#define LDSM2(r, addr) \
    asm volatile("ldmatrix.sync.aligned.m8n8.x2.shared.b16 {%0,%1}, [%2];" \
                 : "=r"((r)[0]), "=r"((r)[1]) : "r"(addr))

#define MMA16816(d, a, b0, b1) \
    asm volatile("mma.sync.aligned.m16n8k16.row.col.f32.bf16.bf16.f32 " \
                 "{%0,%1,%2,%3}, {%4,%5,%6,%7}, {%8,%9}, {%0,%1,%2,%3};" \
                 : "+f"((d)[0]), "+f"((d)[1]), "+f"((d)[2]), "+f"((d)[3]) \
                 : "r"((a)[0]), "r"((a)[1]), "r"((a)[2]), "r"((a)[3]), "r"(b0), "r"(b1))

#define REDV4(p, a, b, c, dd) \
    asm volatile("red.global.add.v4.f32 [%0], {%1,%2,%3,%4};" \
                 :: "l"(p), "f"(a), "f"(b), "f"(c), "f"(dd) : "memory")

// ---------------- zero scratch ----------------
__global__ void k_zero() {
    float4* p = (float4*)&g_A[0][0];
    size_t n4 = (size_t)2 * N_NODES * D / 4;
    size_t stride = (size_t)gridDim.x * blockDim.x;
    for (size_t i = (size_t)blockIdx.x * blockDim.x + threadIdx.x; i < n4; i += stride)
        p[i] = make_float4(0.f, 0.f, 0.f, 0.f);
    if (blockIdx.x == 0 && threadIdx.x < D) {
        g_sum[threadIdx.x] = 0.f;
        g_sq[threadIdx.x]  = 0.f;
    }
}

// ---------------- edge scatter: vector red.global.add.v4 ----------------
__global__ void k_scatter(const float* __restrict__ x,
                          const float* __restrict__ rel,
                          const float* __restrict__ enorm,
                          const int*  __restrict__ esrc,
                          const int*  __restrict__ edst,
                          const int*  __restrict__ etyp,
                          int E, int half) {
    int w    = (blockIdx.x * blockDim.x + threadIdx.x) >> 5;
    int lane = threadIdx.x & 31;
    if (w >= E) return;
    int s = esrc[w];
    int d = edst[w];
    int t = etyp[w];
    float c = enorm[w] * (1.f / 3.f);
    const float4* xr = (const float4*)(x   + (size_t)s * D);
    const float4* rr = (const float4*)(rel + (size_t)t * D);
    float* a = (w < half ? g_A[0] : g_A[1]) + (size_t)d * D;
    #pragma unroll
    for (int i = lane; i < D / 4; i += 32) {
        float4 xv = xr[i];
        float4 rv = rr[i];
        REDV4(a + 4 * i, xv.x * rv.x * c, xv.y * rv.y * c,
                          xv.z * rv.z * c, xv.w * rv.w * c);
    }
}

// ---------------- weight prep: split-bf16, K-major [n][kcat], loop_rel/3 folded ----------------
__global__ void k_prep(const float* __restrict__ in_w,
                       const float* __restrict__ out_w,
                       const float* __restrict__ loop_w,
                       const float* __restrict__ loop_rel) {
    int n    = blockIdx.x;       // 0..199
    int kcat = threadIdx.x;      // 0..623
    int seg  = kcat / SEGW;
    int k    = kcat - seg * SEGW;
    float v = 0.f;
    if (k < D) {
        const float* W = (seg == 0) ? in_w : (seg == 1) ? out_w : loop_w;
        v = W[k * D + n];
        if (seg == 2) v *= loop_rel[k] * (1.f / 3.f);
    }
    __nv_bfloat16 hi = __float2bfloat16(v);
    float lo = v - __bfloat162float(hi);
    g_Bhi[n * KCAT + kcat] = hi;
    g_Blo[n * KCAT + kcat] = __float2bfloat16(lo);
}

// ---------------- node GEMM on HMMA (mma.sync bf16, split 3-term) ----------------
// h[128 x 200] = [A_in | A_out | x] @ Bsplit   per CTA tile.
// 512 threads = 16 warps in 4x4 grid; warp tile 32 rows x 56 cols (2 m16 x 7 n8).
// Shared: A 128x16 bf16 (stride 24 elems = 48B), B 224x16 (stride 24), hi+lo planes.
#define A_STRIDE 48       // bytes per A row (16 bf16 padded to 24)
#define B_STRIDE 48

__global__ __launch_bounds__(512, 1)
void k_gemm(const float* __restrict__ x, float* __restrict__ h) {
    __shared__ __align__(16) char sAhi[128 * A_STRIDE];
    __shared__ __align__(16) char sAlo[128 * A_STRIDE];
    __shared__ __align__(16) char sBhi[NPAD * B_STRIDE];
    __shared__ __align__(16) char sBlo[NPAD * B_STRIDE];

    const int tid  = threadIdx.x;
    const int wid  = tid >> 5;
    const int lane = tid & 31;
    const int wr   = wid >> 2;          // warp row group 0..3
    const int wc   = wid & 3;           // warp col group 0..3
    const int row0 = blockIdx.x * 128;

    const uint32_t uAhi = smem_u32(sAhi);
    const uint32_t uAlo = smem_u32(sAlo);
    const uint32_t uBhi = smem_u32(sBhi);
    const uint32_t uBlo = smem_u32(sBlo);

    // ldmatrix base offsets (lane-dependent parts)
    // A x4: rows (lane&15), k-half (lane>>4)
    const uint32_t aOff = (uint32_t)(lane & 15) * A_STRIDE + (uint32_t)(lane >> 4) * 16;
    // B x4 (2 n-tiles): n = ((lane>>4)<<3) + (lane&7), k-half ((lane>>3)&1)
    const uint32_t bOff4 = ((uint32_t)(((lane >> 4) << 3) + (lane & 7))) * B_STRIDE +
                           (uint32_t)((lane >> 3) & 1) * 16;
    // B x2 (1 n-tile): lanes 0..15 meaningful; mirror for 16..31 to stay in-range
    const uint32_t bOff2 = (uint32_t)(lane & 7) * B_STRIDE + (uint32_t)((lane >> 3) & 1) * 16;

    const float* Asrc[3] = { g_A[0], g_A[1], x };

    float acc[2][7][4];
    #pragma unroll
    for (int m = 0; m < 2; m++)
        #pragma unroll
        for (int n = 0; n < 7; n++)
            #pragma unroll
            for (int q = 0; q < 4; q++) acc[m][n][q] = 0.f;

    // -------- prefetch state --------
    // A: thread t covers row=t>>2, 4 floats at kg=t&3
    const int prow = tid >> 2;
    const int pkg  = tid & 3;
    // B: tasks t and t+512 of 896: plane=t/448, row=(t%448)/2, half=t%2
    float4 a_pf;
    uint4  b_pf0, b_pf1;

    int seg = 0, kb = 0;
    // issue prefetch for chunk 0
    {
        const float* Ap = Asrc[0];
        bool av = (row0 + prow < N_NODES) && (pkg * 4 < D);
        a_pf = av ? *(const float4*)(Ap + (size_t)(row0 + prow) * D + pkg * 4)
                  : make_float4(0.f, 0.f, 0.f, 0.f);
        {
            int t0 = tid;
            int pl = t0 / 448, rem = t0 - pl * 448, rw = rem >> 1, hf = rem & 1;
            const __nv_bfloat16* src = pl ? g_Blo : g_Bhi;
            b_pf0 = (rw < 200) ? *(const uint4*)(src + rw * KCAT + 0 + hf * 8)
                               : make_uint4(0, 0, 0, 0);
        }
        if (tid < 384) {
            int t1 = tid + 512;
            int pl = t1 / 448, rem = t1 - pl * 448, rw = rem >> 1, hf = rem & 1;
            const __nv_bfloat16* src = pl ? g_Blo : g_Bhi;
            b_pf1 = (rw < 200) ? *(const uint4*)(src + rw * KCAT + 0 + hf * 8)
                               : make_uint4(0, 0, 0, 0);
        }
    }

    for (int c = 0; c < NCHUNK; c++) {
        __syncthreads();   // previous compute done; smem free

        // ---- store prefetched chunk c to smem ----
        {
            // A: convert fp32 -> bf16 hi/lo
            __nv_bfloat16 h0 = __float2bfloat16(a_pf.x);
            __nv_bfloat16 h1 = __float2bfloat16(a_pf.y);
            __nv_bfloat16 h2 = __float2bfloat16(a_pf.z);
            __nv_bfloat16 h3 = __float2bfloat16(a_pf.w);
            __nv_bfloat16 l0 = __float2bfloat16(a_pf.x - __bfloat162float(h0));
            __nv_bfloat16 l1 = __float2bfloat16(a_pf.y - __bfloat162float(h1));
            __nv_bfloat16 l2 = __float2bfloat16(a_pf.z - __bfloat162float(h2));
            __nv_bfloat16 l3 = __float2bfloat16(a_pf.w - __bfloat162float(h3));
            uint32_t hij = (uint32_t)__bfloat16_as_ushort(h0) | ((uint32_t)__bfloat16_as_ushort(h1) << 16);
            uint32_t hkl = (uint32_t)__bfloat16_as_ushort(h2) | ((uint32_t)__bfloat16_as_ushort(h3) << 16);
            uint32_t lij = (uint32_t)__bfloat16_as_ushort(l0) | ((uint32_t)__bfloat16_as_ushort(l1) << 16);
            uint32_t lkl = (uint32_t)__bfloat16_as_ushort(l2) | ((uint32_t)__bfloat16_as_ushort(l3) << 16);
            *(uint2*)(sAhi + prow * A_STRIDE + pkg * 8) = make_uint2(hij, hkl);
            *(uint2*)(sAlo + prow * A_STRIDE + pkg * 8) = make_uint2(lij, lkl);
            // B: straight 16B copies
            {
                int t0 = tid;
                int pl = t0 / 448, rem = t0 - pl * 448, rw = rem >> 1, hf = rem & 1;
                char* dst = pl ? sBlo : sBhi;
                *(uint4*)(dst + rw * B_STRIDE + hf * 16) = b_pf0;
            }
            if (tid < 384) {
                int t1 = tid + 512;
                int pl = t1 / 448, rem = t1 - pl * 448, rw = rem >> 1, hf = rem & 1;
                char* dst = pl ? sBlo : sBhi;
                *(uint4*)(dst + rw * B_STRIDE + hf * 16) = b_pf1;
            }
        }
        __syncthreads();

        // ---- issue prefetch for chunk c+1 (hides LDG under MMA) ----
        if (c + 1 < NCHUNK) {
            int nseg = seg, nkb = kb + 16;
            if (nkb == SEGW) { nkb = 0; nseg++; }
            const float* Ap = Asrc[nseg];
            bool av = (row0 + prow < N_NODES) && (nkb + pkg * 4 < D);
            a_pf = av ? *(const float4*)(Ap + (size_t)(row0 + prow) * D + nkb + pkg * 4)
                      : make_float4(0.f, 0.f, 0.f, 0.f);
            int kcat = nseg * SEGW + nkb;
            {
                int t0 = tid;
                int pl = t0 / 448, rem = t0 - pl * 448, rw = rem >> 1, hf = rem & 1;
                const __nv_bfloat16* src = pl ? g_Blo : g_Bhi;
                b_pf0 = (rw < 200) ? *(const uint4*)(src + rw * KCAT + kcat + hf * 8)
                                   : make_uint4(0, 0, 0, 0);
            }
            if (tid < 384) {
                int t1 = tid + 512;
                int pl = t1 / 448, rem = t1 - pl * 448, rw = rem >> 1, hf = rem & 1;
                const __nv_bfloat16* src = pl ? g_Blo : g_Bhi;
                b_pf1 = (rw < 200) ? *(const uint4*)(src + rw * KCAT + kcat + hf * 8)
                                   : make_uint4(0, 0, 0, 0);
            }
        }

        // ---- compute chunk c ----
        {
            uint32_t ah[2][4], al[2][4];
            #pragma unroll
            for (int mt = 0; mt < 2; mt++) {
                uint32_t rbase = (uint32_t)(wr * 32 + mt * 16) * A_STRIDE;
                LDSM4(ah[mt], uAhi + rbase + aOff);
                LDSM4(al[mt], uAlo + rbase + aOff);
            }
            #pragma unroll
            for (int np = 0; np < 3; np++) {   // n-tile pairs 0..5
                uint32_t nbase = (uint32_t)(wc * 56 + np * 16) * B_STRIDE;
                uint32_t bh[4], bl[4];
                LDSM4(bh, uBhi + nbase + bOff4);
                LDSM4(bl, uBlo + nbase + bOff4);
                #pragma unroll
                for (int mt = 0; mt < 2; mt++) {
                    MMA16816(acc[mt][2 * np],     ah[mt], bh[0], bh[1]);
                    MMA16816(acc[mt][2 * np],     ah[mt], bl[0], bl[1]);
                    MMA16816(acc[mt][2 * np],     al[mt], bh[0], bh[1]);
                    MMA16816(acc[mt][2 * np + 1], ah[mt], bh[2], bh[3]);
                    MMA16816(acc[mt][2 * np + 1], ah[mt], bl[2], bl[3]);
                    MMA16816(acc[mt][2 * np + 1], al[mt], bh[2], bh[3]);
                }
            }
            {   // n-tile 6 (single)
                uint32_t nbase = (uint32_t)(wc * 56 + 48) * B_STRIDE;
                uint32_t bh[2], bl[2];
                LDSM2(bh, uBhi + nbase + bOff2);
                LDSM2(bl, uBlo + nbase + bOff2);
                #pragma unroll
                for (int mt = 0; mt < 2; mt++) {
                    MMA16816(acc[mt][6], ah[mt], bh[0], bh[1]);
                    MMA16816(acc[mt][6], ah[mt], bl[0], bl[1]);
                    MMA16816(acc[mt][6], al[mt], bh[0], bh[1]);
                }
            }
        }

        kb += 16;
        if (kb == SEGW) { kb = 0; seg++; }
    }

    // ---- epilogue: write accumulators straight to h ----
    #pragma unroll
    for (int mt = 0; mt < 2; mt++) {
        int rlo = row0 + wr * 32 + mt * 16 + (lane >> 2);
        int rhi = rlo + 8;
        #pragma unroll
        for (int nt = 0; nt < 7; nt++) {
            int col = wc * 56 + nt * 8 + 2 * (lane & 3);
            if (col < D) {
                if (rlo < N_NODES)
                    *(float2*)(h + (size_t)rlo * D + col) = make_float2(acc[mt][nt][0], acc[mt][nt][1]);
                if (rhi < N_NODES)
                    *(float2*)(h + (size_t)rhi * D + col) = make_float2(acc[mt][nt][2], acc[mt][nt][3]);
            }
        }
    }
}

// ---------------- per-column sum / sumsq for BatchNorm ----------------
__global__ void k_stats(const float* __restrict__ h) {
    int col = threadIdx.x;   // 0..199
    float s = 0.f, q = 0.f;
    #pragma unroll 4
    for (int r = blockIdx.x; r < N_NODES; r += 1000) {
        float v = h[(size_t)r * D + col];
        s += v;
        q += v * v;
    }
    atomicAdd(&g_sum[col], s);
    atomicAdd(&g_sq[col],  q);
}

// ---------------- BatchNorm normalize (in place, float4) ----------------
__global__ void k_norm(float* __restrict__ h,
                       const float* __restrict__ gamma,
                       const float* __restrict__ beta) {
    __shared__ float s_scale[D];
    __shared__ float s_shift[D];
    if (threadIdx.x < D) {
        const float invN = 1.f / (float)N_NODES;
        float mean = g_sum[threadIdx.x] * invN;
        float var  = g_sq[threadIdx.x] * invN - mean * mean;
        float inv  = rsqrtf(var + BN_EPS);
        float sc   = inv * gamma[threadIdx.x];
        s_scale[threadIdx.x] = sc;
        s_shift[threadIdx.x] = beta[threadIdx.x] - mean * sc;
    }
    __syncthreads();
    float4* h4 = (float4*)h;
    size_t n4 = (size_t)N_NODES * D / 4;
    size_t stride = (size_t)gridDim.x * blockDim.x;
    for (size_t i = (size_t)blockIdx.x * blockDim.x + threadIdx.x; i < n4; i += stride) {
        int c = (int)((i * 4) % D);
        float4 v = h4[i];
        v.x = v.x * s_scale[c]     + s_shift[c];
        v.y = v.y * s_scale[c + 1] + s_shift[c + 1];
        v.z = v.z * s_scale[c + 2] + s_shift[c + 2];
        v.w = v.w * s_scale[c + 3] + s_shift[c + 3];
        h4[i] = v;
    }
}

// ---------------- rel_out = rel_repr @ w_rel (tiny, fp32 exact) ----------------
__global__ void k_rel(const float* __restrict__ rel,
                      const float* __restrict__ w,
                      float* __restrict__ out) {
    int i = blockIdx.x;
    int j = threadIdx.x;
    float s = 0.f;
    #pragma unroll 4
    for (int k = 0; k < D; k++)
        s = fmaf(rel[i * D + k], w[k * D + j], s);
    out[i * D + j] = s;
}

// ---------------- launch ----------------
extern "C" void kernel_launch(void* const* d_in, const int* in_sizes, int n_in,
                              void* d_out, int out_size) {
    const float* x        = (const float*)d_in[0];
    const float* rel      = (const float*)d_in[1];
    const float* enorm    = (const float*)d_in[2];
    const float* in_w     = (const float*)d_in[3];
    const float* out_w    = (const float*)d_in[4];
    const float* loop_w   = (const float*)d_in[5];
    const float* loop_rel = (const float*)d_in[6];
    const float* w_rel    = (const float*)d_in[7];
    const float* gamma    = (const float*)d_in[8];
    const float* beta     = (const float*)d_in[9];
    const int*   esrc     = (const int*)d_in[10];
    const int*   edst     = (const int*)d_in[11];
    const int*   etyp     = (const int*)d_in[12];

    float* h      = (float*)d_out;
    float* relout = h + (size_t)N_NODES * D;

    int E = in_sizes[2];           // 400000
    int half = E / 2;

    k_zero<<<1024, 256>>>();
    k_scatter<<<(E + 7) / 8, 256>>>(x, rel, enorm, esrc, edst, etyp, E, half);
    k_prep<<<200, 624>>>(in_w, out_w, loop_w, loop_rel);
    k_gemm<<<N_TILES, 512>>>(x, h);
    k_stats<<<1000, 200>>>(h);
    k_norm<<<1024, 256>>>(h, gamma, beta);
    k_rel<<<200, 200>>>(rel, w_rel, relout);
}

// round 13
// speedup vs baseline: 5.2308x; 1.1215x over previous
#include <cuda_runtime.h>
#include <cuda_bf16.h>
#include <cstdint>

#define N_NODES 100000
#define N_RELS  200
#define D       200
#define BN_EPS  1e-5f

#define SEGW 208          // per-segment padded K (200 real + 8 zero)
#define KCAT 624          // 3 * SEGW
#define NCHUNK 39         // 39 chunks of K=16
#define NPAD 224          // padded N for the GEMM (200 real)
#define N_TILES 782       // ceil(100000/128)

// ---------------- scratch (no cudaMalloc allowed) ----------------
__device__ float g_A[2][(size_t)N_NODES * D];   // in / out edge accumulators
__device__ float g_sum[D];
__device__ float g_sq[D];
__device__ __nv_bfloat16 g_Bhi[200 * KCAT];     // weights, split-bf16, K-major [n][kcat]
__device__ __nv_bfloat16 g_Blo[200 * KCAT];

// ---------------- PTX helpers (base ISA only — no sm_103a features!) ----------------
__device__ __forceinline__ uint32_t smem_u32(const void* p) {
    uint32_t a;
    asm("{ .reg .u64 t; cvta.to.shared.u64 t, %1; cvt.u32.u64 %0, t; }" : "=r"(a) : "l"(p));
    return a;
}

#define LDSM4(r, addr) \
    asm volatile("ldmatrix.sync.aligned.m8n8.x4.shared.b16 {%0,%1,%2,%3}, [%4];" \
                 : "=r"((r)[0]), "=r"((r)[1]), "=r"((r)[2]), "=r"((r)[3]) : "r"(addr))
#define LDSM2(r, addr) \
    asm volatile("ldmatrix.sync.aligned.m8n8.x2.shared.b16 {%0,%1}, [%2];" \
                 : "=r"((r)[0]), "=r"((r)[1]) : "r"(addr))

#define MMA16816(d, a, b0, b1) \
    asm volatile("mma.sync.aligned.m16n8k16.row.col.f32.bf16.bf16.f32 " \
                 "{%0,%1,%2,%3}, {%4,%5,%6,%7}, {%8,%9}, {%0,%1,%2,%3};" \
                 : "+f"((d)[0]), "+f"((d)[1]), "+f"((d)[2]), "+f"((d)[3]) \
                 : "r"((a)[0]), "r"((a)[1]), "r"((a)[2]), "r"((a)[3]), "r"(b0), "r"(b1))

#define REDV4(p, a, b, c, dd) \
    asm volatile("red.global.add.v4.f32 [%0], {%1,%2,%3,%4};" \
                 :: "l"(p), "f"(a), "f"(b), "f"(c), "f"(dd) : "memory")

// ---------------- zero scratch ----------------
__global__ void k_zero() {
    float4* p = (float4*)&g_A[0][0];
    size_t n4 = (size_t)2 * N_NODES * D / 4;
    size_t stride = (size_t)gridDim.x * blockDim.x;
    for (size_t i = (size_t)blockIdx.x * blockDim.x + threadIdx.x; i < n4; i += stride)
        p[i] = make_float4(0.f, 0.f, 0.f, 0.f);
    if (blockIdx.x == 0 && threadIdx.x < D) {
        g_sum[threadIdx.x] = 0.f;
        g_sq[threadIdx.x]  = 0.f;
    }
}

// ---------------- edge scatter: vector red.global.add.v4 ----------------
__global__ void k_scatter(const float* __restrict__ x,
                          const float* __restrict__ rel,
                          const float* __restrict__ enorm,
                          const int*  __restrict__ esrc,
                          const int*  __restrict__ edst,
                          const int*  __restrict__ etyp,
                          int E, int half) {
    int w    = (blockIdx.x * blockDim.x + threadIdx.x) >> 5;
    int lane = threadIdx.x & 31;
    if (w >= E) return;
    int s = esrc[w];
    int d = edst[w];
    int t = etyp[w];
    float c = enorm[w] * (1.f / 3.f);
    const float4* xr = (const float4*)(x   + (size_t)s * D);
    const float4* rr = (const float4*)(rel + (size_t)t * D);
    float* a = (w < half ? g_A[0] : g_A[1]) + (size_t)d * D;
    #pragma unroll
    for (int i = lane; i < D / 4; i += 32) {
        float4 xv = xr[i];
        float4 rv = rr[i];
        REDV4(a + 4 * i, xv.x * rv.x * c, xv.y * rv.y * c,
                          xv.z * rv.z * c, xv.w * rv.w * c);
    }
}

// ---------------- weight prep: split-bf16, K-major [n][kcat], loop_rel/3 folded ----------------
__global__ void k_prep(const float* __restrict__ in_w,
                       const float* __restrict__ out_w,
                       const float* __restrict__ loop_w,
                       const float* __restrict__ loop_rel) {
    int n    = blockIdx.x;       // 0..199
    int kcat = threadIdx.x;      // 0..623
    int seg  = kcat / SEGW;
    int k    = kcat - seg * SEGW;
    float v = 0.f;
    if (k < D) {
        const float* W = (seg == 0) ? in_w : (seg == 1) ? out_w : loop_w;
        v = W[k * D + n];
        if (seg == 2) v *= loop_rel[k] * (1.f / 3.f);
    }
    __nv_bfloat16 hi = __float2bfloat16(v);
    float lo = v - __bfloat162float(hi);
    g_Bhi[n * KCAT + kcat] = hi;
    g_Blo[n * KCAT + kcat] = __float2bfloat16(lo);
}

// ---------------- node GEMM on HMMA: double-buffered, fused BN stats ----------------
// h[128 x 200] = [A_in | A_out | x] @ Bsplit   per CTA tile.
// 512 threads = 16 warps in 4x4 grid; warp tile 32 rows x 56 cols (2 m16 x 7 n8).
#define A_STRIDE 48       // bytes per A row (16 bf16 padded to 24)
#define B_STRIDE 48
#define A_HI_OFF 0
#define A_LO_OFF 6144     // 128*48
#define B_HI_OFF 12288
#define B_LO_OFF 23040    // 12288 + 224*48
#define BUF_SZ   33792    // 23040 + 224*48
#define STAT_OFF (2 * BUF_SZ)          // s_sum[200], s_sq[200]
#define SMEM_DYN (2 * BUF_SZ + 2 * 200 * 4)   // 69184

__global__ __launch_bounds__(512, 1)
void k_gemm(const float* __restrict__ x, float* __restrict__ h) {
    extern __shared__ __align__(16) char smem[];
    const int tid  = threadIdx.x;
    const int wid  = tid >> 5;
    const int lane = tid & 31;
    const int wr   = wid >> 2;          // warp row group 0..3
    const int wc   = wid & 3;           // warp col group 0..3
    const int row0 = blockIdx.x * 128;

    const uint32_t uBase = smem_u32(smem);
    float* s_sum = (float*)(smem + STAT_OFF);
    float* s_sq  = s_sum + 200;
    if (tid < 200) { s_sum[tid] = 0.f; s_sq[tid] = 0.f; }

    // ldmatrix lane offsets
    const uint32_t aOff = (uint32_t)(lane & 15) * A_STRIDE + (uint32_t)(lane >> 4) * 16;
    const uint32_t bOff4 = ((uint32_t)(((lane >> 4) << 3) + (lane & 7))) * B_STRIDE +
                           (uint32_t)((lane >> 3) & 1) * 16;
    const uint32_t bOff2 = (uint32_t)(lane & 7) * B_STRIDE + (uint32_t)((lane >> 3) & 1) * 16;

    const float* Asrc[3] = { g_A[0], g_A[1], x };

    float acc[2][7][4];
    #pragma unroll
    for (int m = 0; m < 2; m++)
        #pragma unroll
        for (int n = 0; n < 7; n++)
            #pragma unroll
            for (int q = 0; q < 4; q++) acc[m][n][q] = 0.f;

    // prefetch task mapping
    const int prow = tid >> 2;          // A row
    const int pkg  = tid & 3;           // A k-group (4 floats)
    float4 a_pf;
    uint4  b_pf0, b_pf1;

    // ---- helpers as lambdas ----
    auto prefetch = [&](int seg, int kb) {
        const float* Ap = Asrc[seg];
        bool av = (row0 + prow < N_NODES) && (kb + pkg * 4 < D);
        a_pf = av ? *(const float4*)(Ap + (size_t)(row0 + prow) * D + kb + pkg * 4)
                  : make_float4(0.f, 0.f, 0.f, 0.f);
        int kcat = seg * SEGW + kb;
        {
            int t0 = tid;
            int pl = t0 / 448, rem = t0 - pl * 448, rw = rem >> 1, hf = rem & 1;
            const __nv_bfloat16* src = pl ? g_Blo : g_Bhi;
            b_pf0 = (rw < 200) ? *(const uint4*)(src + rw * KCAT + kcat + hf * 8)
                               : make_uint4(0, 0, 0, 0);
        }
        if (tid < 384) {
            int t1 = tid + 512;
            int pl = t1 / 448, rem = t1 - pl * 448, rw = rem >> 1, hf = rem & 1;
            const __nv_bfloat16* src = pl ? g_Blo : g_Bhi;
            b_pf1 = (rw < 200) ? *(const uint4*)(src + rw * KCAT + kcat + hf * 8)
                               : make_uint4(0, 0, 0, 0);
        }
    };

    auto store = [&](int buf) {
        char* base = smem + buf * BUF_SZ;
        __nv_bfloat16 h0 = __float2bfloat16(a_pf.x);
        __nv_bfloat16 h1 = __float2bfloat16(a_pf.y);
        __nv_bfloat16 h2 = __float2bfloat16(a_pf.z);
        __nv_bfloat16 h3 = __float2bfloat16(a_pf.w);
        __nv_bfloat16 l0 = __float2bfloat16(a_pf.x - __bfloat162float(h0));
        __nv_bfloat16 l1 = __float2bfloat16(a_pf.y - __bfloat162float(h1));
        __nv_bfloat16 l2 = __float2bfloat16(a_pf.z - __bfloat162float(h2));
        __nv_bfloat16 l3 = __float2bfloat16(a_pf.w - __bfloat162float(h3));
        uint32_t hij = (uint32_t)__bfloat16_as_ushort(h0) | ((uint32_t)__bfloat16_as_ushort(h1) << 16);
        uint32_t hkl = (uint32_t)__bfloat16_as_ushort(h2) | ((uint32_t)__bfloat16_as_ushort(h3) << 16);
        uint32_t lij = (uint32_t)__bfloat16_as_ushort(l0) | ((uint32_t)__bfloat16_as_ushort(l1) << 16);
        uint32_t lkl = (uint32_t)__bfloat16_as_ushort(l2) | ((uint32_t)__bfloat16_as_ushort(l3) << 16);
        *(uint2*)(base + A_HI_OFF + prow * A_STRIDE + pkg * 8) = make_uint2(hij, hkl);
        *(uint2*)(base + A_LO_OFF + prow * A_STRIDE + pkg * 8) = make_uint2(lij, lkl);
        {
            int t0 = tid;
            int pl = t0 / 448, rem = t0 - pl * 448, rw = rem >> 1, hf = rem & 1;
            char* dst = base + (pl ? B_LO_OFF : B_HI_OFF);
            *(uint4*)(dst + rw * B_STRIDE + hf * 16) = b_pf0;
        }
        if (tid < 384) {
            int t1 = tid + 512;
            int pl = t1 / 448, rem = t1 - pl * 448, rw = rem >> 1, hf = rem & 1;
            char* dst = base + (pl ? B_LO_OFF : B_HI_OFF);
            *(uint4*)(dst + rw * B_STRIDE + hf * 16) = b_pf1;
        }
    };

    // ---- prologue ----
    prefetch(0, 0);
    store(0);
    __syncthreads();
    prefetch(0, 16);          // chunk 1 in flight

    int seg = 0, kb = 16;     // (seg,kb) of the chunk currently prefetched
    for (int c = 0; c < NCHUNK; c++) {
        const uint32_t buf = (uint32_t)(c & 1) * BUF_SZ;
        const uint32_t uAhi = uBase + buf + A_HI_OFF;
        const uint32_t uAlo = uBase + buf + A_LO_OFF;
        const uint32_t uBhi = uBase + buf + B_HI_OFF;
        const uint32_t uBlo = uBase + buf + B_LO_OFF;

        // ---- compute chunk c (MMA hides the in-flight LDG prefetch) ----
        uint32_t ah[2][4], al[2][4];
        #pragma unroll
        for (int mt = 0; mt < 2; mt++) {
            uint32_t rbase = (uint32_t)(wr * 32 + mt * 16) * A_STRIDE;
            LDSM4(ah[mt], uAhi + rbase + aOff);
            LDSM4(al[mt], uAlo + rbase + aOff);
        }
        #pragma unroll
        for (int np = 0; np < 3; np++) {
            uint32_t nbase = (uint32_t)(wc * 56 + np * 16) * B_STRIDE;
            uint32_t bh[4], bl[4];
            LDSM4(bh, uBhi + nbase + bOff4);
            LDSM4(bl, uBlo + nbase + bOff4);
            #pragma unroll
            for (int mt = 0; mt < 2; mt++) {
                MMA16816(acc[mt][2 * np],     ah[mt], bh[0], bh[1]);
                MMA16816(acc[mt][2 * np],     ah[mt], bl[0], bl[1]);
                MMA16816(acc[mt][2 * np],     al[mt], bh[0], bh[1]);
                MMA16816(acc[mt][2 * np + 1], ah[mt], bh[2], bh[3]);
                MMA16816(acc[mt][2 * np + 1], ah[mt], bl[2], bl[3]);
                MMA16816(acc[mt][2 * np + 1], al[mt], bh[2], bh[3]);
            }
        }
        {
            uint32_t nbase = (uint32_t)(wc * 56 + 48) * B_STRIDE;
            uint32_t bh[2], bl[2];
            LDSM2(bh, uBhi + nbase + bOff2);
            LDSM2(bl, uBlo + nbase + bOff2);
            #pragma unroll
            for (int mt = 0; mt < 2; mt++) {
                MMA16816(acc[mt][6], ah[mt], bh[0], bh[1]);
                MMA16816(acc[mt][6], ah[mt], bl[0], bl[1]);
                MMA16816(acc[mt][6], al[mt], bh[0], bh[1]);
            }
        }

        // ---- store prefetched chunk c+1 into alternate buffer, start LDG c+2 ----
        if (c + 1 < NCHUNK) {
            store((c + 1) & 1);
            kb += 16;
            if (kb == SEGW) { kb = 0; seg++; }
            if (c + 2 < NCHUNK) prefetch(seg, kb);
        }
        __syncthreads();
    }

    // ---- epilogue 1: write h ----
    #pragma unroll
    for (int mt = 0; mt < 2; mt++) {
        int rlo = row0 + wr * 32 + mt * 16 + (lane >> 2);
        int rhi = rlo + 8;
        #pragma unroll
        for (int nt = 0; nt < 7; nt++) {
            int col = wc * 56 + nt * 8 + 2 * (lane & 3);
            if (col < D) {
                if (rlo < N_NODES)
                    *(float2*)(h + (size_t)rlo * D + col) = make_float2(acc[mt][nt][0], acc[mt][nt][1]);
                if (rhi < N_NODES)
                    *(float2*)(h + (size_t)rhi * D + col) = make_float2(acc[mt][nt][2], acc[mt][nt][3]);
            }
        }
    }

    // ---- epilogue 2: fused BN stats (sum / sumsq per column) ----
    #pragma unroll
    for (int nt = 0; nt < 7; nt++) {
        float s0 = acc[0][nt][0] + acc[0][nt][2] + acc[1][nt][0] + acc[1][nt][2];
        float s1 = acc[0][nt][1] + acc[0][nt][3] + acc[1][nt][1] + acc[1][nt][3];
        float q0 = acc[0][nt][0]*acc[0][nt][0] + acc[0][nt][2]*acc[0][nt][2]
                 + acc[1][nt][0]*acc[1][nt][0] + acc[1][nt][2]*acc[1][nt][2];
        float q1 = acc[0][nt][1]*acc[0][nt][1] + acc[0][nt][3]*acc[0][nt][3]
                 + acc[1][nt][1]*acc[1][nt][1] + acc[1][nt][3]*acc[1][nt][3];
        // butterfly over the 8 row-groups (lane bits 2,3,4)
        #pragma unroll
        for (int m = 4; m <= 16; m <<= 1) {
            s0 += __shfl_xor_sync(0xffffffffu, s0, m);
            s1 += __shfl_xor_sync(0xffffffffu, s1, m);
            q0 += __shfl_xor_sync(0xffffffffu, q0, m);
            q1 += __shfl_xor_sync(0xffffffffu, q1, m);
        }
        if (lane < 4) {
            int col = wc * 56 + nt * 8 + 2 * lane;
            if (col < D) {
                atomicAdd(&s_sum[col],     s0);
                atomicAdd(&s_sq[col],      q0);
                atomicAdd(&s_sum[col + 1], s1);
                atomicAdd(&s_sq[col + 1],  q1);
            }
        }
    }
    __syncthreads();
    if (tid < D) {
        atomicAdd(&g_sum[tid], s_sum[tid]);
        atomicAdd(&g_sq[tid],  s_sq[tid]);
    }
}

// ---------------- BatchNorm normalize (in place, float4) ----------------
__global__ void k_norm(float* __restrict__ h,
                       const float* __restrict__ gamma,
                       const float* __restrict__ beta) {
    __shared__ float s_scale[D];
    __shared__ float s_shift[D];
    if (threadIdx.x < D) {
        const float invN = 1.f / (float)N_NODES;
        float mean = g_sum[threadIdx.x] * invN;
        float var  = g_sq[threadIdx.x] * invN - mean * mean;
        float inv  = rsqrtf(var + BN_EPS);
        float sc   = inv * gamma[threadIdx.x];
        s_scale[threadIdx.x] = sc;
        s_shift[threadIdx.x] = beta[threadIdx.x] - mean * sc;
    }
    __syncthreads();
    float4* h4 = (float4*)h;
    size_t n4 = (size_t)N_NODES * D / 4;
    size_t stride = (size_t)gridDim.x * blockDim.x;
    for (size_t i = (size_t)blockIdx.x * blockDim.x + threadIdx.x; i < n4; i += stride) {
        int c = (int)((i * 4) % D);
        float4 v = h4[i];
        v.x = v.x * s_scale[c]     + s_shift[c];
        v.y = v.y * s_scale[c + 1] + s_shift[c + 1];
        v.z = v.z * s_scale[c + 2] + s_shift[c + 2];
        v.w = v.w * s_scale[c + 3] + s_shift[c + 3];
        h4[i] = v;
    }
}

// ---------------- rel_out = rel_repr @ w_rel (tiny, fp32 exact) ----------------
__global__ void k_rel(const float* __restrict__ rel,
                      const float* __restrict__ w,
                      float* __restrict__ out) {
    int i = blockIdx.x;
    int j = threadIdx.x;
    float s = 0.f;
    #pragma unroll 4
    for (int k = 0; k < D; k++)
        s = fmaf(rel[i * D + k], w[k * D + j], s);
    out[i * D + j] = s;
}

// ---------------- launch ----------------
extern "C" void kernel_launch(void* const* d_in, const int* in_sizes, int n_in,
                              void* d_out, int out_size) {
    const float* x        = (const float*)d_in[0];
    const float* rel      = (const float*)d_in[1];
    const float* enorm    = (const float*)d_in[2];
    const float* in_w     = (const float*)d_in[3];
    const float* out_w    = (const float*)d_in[4];
    const float* loop_w   = (const float*)d_in[5];
    const float* loop_rel = (const float*)d_in[6];
    const float* w_rel    = (const float*)d_in[7];
    const float* gamma    = (const float*)d_in[8];
    const float* beta     = (const float*)d_in[9];
    const int*   esrc     = (const int*)d_in[10];
    const int*   edst     = (const int*)d_in[11];
    const int*   etyp     = (const int*)d_in[12];

    float* h      = (float*)d_out;
    float* relout = h + (size_t)N_NODES * D;

    int E = in_sizes[2];           // 400000
    int half = E / 2;

    cudaFuncSetAttribute(k_gemm, cudaFuncAttributeMaxDynamicSharedMemorySize, SMEM_DYN);

    k_zero<<<2048, 256>>>();
    k_scatter<<<(E + 7) / 8, 256>>>(x, rel, enorm, esrc, edst, etyp, E, half);
    k_prep<<<200, 624>>>(in_w, out_w, loop_w, loop_rel);
    k_gemm<<<N_TILES, 512, SMEM_DYN>>>(x, h);
    k_norm<<<1024, 256>>>(h, gamma, beta);
    k_rel<<<200, 200>>>(rel, w_rel, relout);
}